// round 7
// baseline (speedup 1.0000x reference)
#include <cuda_runtime.h>
#include <cuda_bf16.h>

// CausalSequenceCML: 16 fused steps of depthwise-causal-conv logistic CML.
// B=4, T=4096, C=512, K=4, STEPS=16.
//
// Round-7: ZERO-HALO. One CTA = one (channel, batch), covering all T=4096:
// 8 warps x 32 lanes x 16 cells. No tile overlap -> FFMA count is the
// algebraic minimum (4096*16*5 per channel-batch), -11% vs R5.
//  - intra-warp halo: 3x shfl_up
//  - inter-warp halo: 3 floats via 288B double-buffered smem + 1 barrier/step
//  - g[16]+D[16] = 32 state regs: no spill under launch_bounds(256,4)
// Global I/O is channel-strided; sectors shared by 8 channel-CTAs via L2.

#define Bdim 4
#define Tdim 4096
#define Cdim 512
#define NSTEPS 16
#define NW 8                  // warps per CTA
#define LL 16                 // cells per lane (NW*32*LL = 4096 = Tdim)

__global__ void __launch_bounds__(32 * NW, 4)
cml_kernel(const float* __restrict__ drive,
           const float* __restrict__ r,
           const float* __restrict__ eps,
           const float* __restrict__ beta,
           const float* __restrict__ Kc,
           float* __restrict__ out)
{
    // inter-warp boundary m' values: [buf][warp+1][3]; slot 0 = zeros
    __shared__ float buf[2][NW + 1][4];

    const int tid  = threadIdx.x;
    const int lane = tid & 31;
    const int w    = tid >> 5;
    const int cg   = blockIdx.x;             // channel
    const int b    = blockIdx.y;             // batch
    const int base = b * (Tdim * Cdim) + cg;
    const int t0   = (w * 32 + lane) * LL;   // this thread's first time index

    if (tid < 3) { buf[0][0][tid] = 0.0f; buf[1][0][tid] = 0.0f; }

    // per-channel constants (uniform across CTA); fold r into conv weights
    const float rr = r[cg];
    const float ee = eps[cg];
    const float bb = beta[cg];
    const float k0 = Kc[cg * 4 + 0];
    const float k1 = Kc[cg * 4 + 1];
    const float k2 = Kc[cg * 4 + 2];
    const float k3 = Kc[cg * 4 + 3];
    const float onemb = 1.0f - bb;
    const float A  = onemb * (1.0f - ee);
    const float Bc = onemb * ee;
    const float v3 = fmaf(Bc, k3, A) * rr;   // coeff of m'[t]
    const float v2 = Bc * k2 * rr;           // m'[t-1]
    const float v1 = Bc * k1 * rr;           // m'[t-2]
    const float v0 = Bc * k0 * rr;           // m'[t-3]

    // load drive (channel-strided; sectors L2-shared across channel-CTAs)
    float g[LL], D[LL];
#pragma unroll
    for (int i = 0; i < LL; i++) {
        const float d = drive[base + (t0 + i) * Cdim];
        g[i] = d;
        D[i] = bb * d;
    }
    __syncthreads();   // covers buf zero-init

    // ---- 16 fused steps ----
#pragma unroll 1
    for (int step = 0; step < NSTEPS; step++) {
        // m' of this lane's last 3 cells (pre-update values)
        const float tA = fmaf(-g[LL-3], g[LL-3], g[LL-3]);
        const float tB = fmaf(-g[LL-2], g[LL-2], g[LL-2]);
        const float tC = fmaf(-g[LL-1], g[LL-1], g[LL-1]);

        // inter-warp: lane 31 publishes its tail to slot w+1
        const int pb = step & 1;
        if (lane == 31) {
            buf[pb][w + 1][0] = tA;
            buf[pb][w + 1][1] = tB;
            buf[pb][w + 1][2] = tC;
        }
        // intra-warp: shfl up by one lane
        const float s1 = __shfl_up_sync(0xffffffffu, tC, 1);
        const float s2 = __shfl_up_sync(0xffffffffu, tB, 1);
        const float s3 = __shfl_up_sync(0xffffffffu, tA, 1);

        __syncthreads();

        // broadcast read of previous warp's tail (slot w; w=0 -> zeros)
        const float p1 = buf[pb][w][2];
        const float p2 = buf[pb][w][1];
        const float p3 = buf[pb][w][0];
        float m1 = lane ? s1 : p1;
        float m2 = lane ? s2 : p2;
        float m3 = lane ? s3 : p3;

        // sweep: 5 FMA per cell; tails reused for the last 3
#pragma unroll
        for (int i = 0; i < LL; i++) {
            const float gi = g[i];
            const float m0 = (i < LL - 3) ? fmaf(-gi, gi, gi)
                           : (i == LL - 3 ? tA : (i == LL - 2 ? tB : tC));
            float acc = fmaf(v3, m0, D[i]);
            acc = fmaf(v2, m1, acc);
            acc = fmaf(v1, m2, acc);
            g[i] = fmaf(v0, m3, acc);
            m3 = m2; m2 = m1; m1 = m0;
        }
    }

    // clip + store (channel-strided, L2 write-combined across channel-CTAs)
#pragma unroll
    for (int i = 0; i < LL; i++) {
        const float v = fminf(fmaxf(g[i], 1.0e-4f), 1.0f - 1.0e-4f);
        out[base + (t0 + i) * Cdim] = v;
    }
}

extern "C" void kernel_launch(void* const* d_in, const int* in_sizes, int n_in,
                              void* d_out, int out_size)
{
    const float* drive = (const float*)d_in[0];
    const float* r     = (const float*)d_in[1];
    const float* eps   = (const float*)d_in[2];
    const float* beta  = (const float*)d_in[3];
    const float* Kc    = (const float*)d_in[4];
    float* out = (float*)d_out;

    dim3 grid(Cdim, Bdim);                // 512 x 4 = 2048 CTAs
    cml_kernel<<<grid, 32 * NW>>>(drive, r, eps, beta, Kc, out);
}

// round 8
// speedup vs baseline: 1.7498x; 1.7498x over previous
#include <cuda_runtime.h>
#include <cuda_bf16.h>

// CausalSequenceCML: 16 fused steps of depthwise-causal-conv logistic CML.
// B=4, T=4096, C=512, K=4, STEPS=16.
//
// Round-8: R5 warp-per-channel skeleton (best known: 51.2us), geometry
// retuned at the FFMA rt=2 cap:
//  - LL=23 cells/lane, TILE=736, VALID=688, NTILES=6: halo amp
//    6*736/4096 = 1.078 (vs 1.125) -> -4.2% FFMA count.
//  - launch_bounds(256,3): 85-reg cap fits g[23]+D[23]+overhead (~74 regs)
//    WITHOUT spilling (R6 lesson: the 64-reg/occ-4 cap spills at LL>=20).
//    R1/R3 showed occ ~35% sustains ~93% of the FFMA-pipe cap.
//  - hot loop unchanged: 3 shfls per step, no smem, no barriers.

#define Bdim 4
#define Tdim 4096
#define Cdim 512
#define NSTEPS 16
#define WC 8                  // channels (warps) per block
#define LL 23                 // cells per lane
#define TILE (32 * LL)        // 736
#define HALO 48               // 3 * NSTEPS
#define VALID (TILE - HALO)   // 688
#define NTILES 6              // 6*688 = 4128 >= 4096
#define ROWP (TILE + 1)       // smem row pad

__global__ void __launch_bounds__(32 * WC, 3)
cml_kernel(const float* __restrict__ drive,
           const float* __restrict__ r,
           const float* __restrict__ eps,
           const float* __restrict__ beta,
           const float* __restrict__ Kc,
           float* __restrict__ out)
{
    __shared__ float st[WC][ROWP];     // staging: [channel][time]

    const int tid  = threadIdx.x;
    const int lane = tid & 31;
    const int w    = tid >> 5;               // warp = channel within block
    const int c0   = blockIdx.y * WC;
    const int cg   = c0 + w;
    const int b    = blockIdx.z;
    const int gt0  = (int)blockIdx.x * VALID - HALO;
    const int base = b * (Tdim * Cdim);

    // ---- stage: global -> smem [c][t] ----
#pragma unroll
    for (int it = 0; it < TILE / 32; it++) {
        const int idx = it * (32 * WC) + tid;
        const int t = idx >> 3;
        const int c = idx & 7;
        const int gt = gt0 + t;
        float d = 0.0f;
        if (gt >= 0 && gt < Tdim)
            d = drive[base + gt * Cdim + c0 + c];
        st[c][t] = d;
    }

    // per-channel (warp-uniform) constants; fold r into conv weights
    const float rr = r[cg];
    const float ee = eps[cg];
    const float bb = beta[cg];
    const float k0 = Kc[cg * 4 + 0];
    const float k1 = Kc[cg * 4 + 1];
    const float k2 = Kc[cg * 4 + 2];
    const float k3 = Kc[cg * 4 + 3];
    const float onemb = 1.0f - bb;
    const float A  = onemb * (1.0f - ee);
    const float Bc = onemb * ee;
    const float v3 = fmaf(Bc, k3, A) * rr;   // coeff of m'[t]
    const float v2 = Bc * k2 * rr;           // m'[t-1]
    const float v1 = Bc * k1 * rr;           // m'[t-2]
    const float v0 = Bc * k0 * rr;           // m'[t-3]

    __syncthreads();

    // ---- smem -> registers (lane-major time) ----
    float g[LL], D[LL];
#pragma unroll
    for (int i = 0; i < LL; i++) {
        const float d = st[w][lane * LL + i];
        g[i] = d;
        D[i] = bb * d;
    }

    // ---- 16 fused steps; warp-synchronous halo via shfl ----
#pragma unroll 1
    for (int step = 0; step < NSTEPS; step++) {
        // m' of this lane's last 3 cells (pre-update values)
        const float gA = g[LL - 3], gB = g[LL - 2], gC = g[LL - 1];
        const float tA = fmaf(-gA, gA, gA);
        const float tB = fmaf(-gB, gB, gB);
        const float tC = fmaf(-gC, gC, gC);
        float m1 = __shfl_up_sync(0xffffffffu, tC, 1);
        float m2 = __shfl_up_sync(0xffffffffu, tB, 1);
        float m3 = __shfl_up_sync(0xffffffffu, tA, 1);
        if (lane == 0) { m1 = 0.0f; m2 = 0.0f; m3 = 0.0f; }

#pragma unroll
        for (int i = 0; i < LL; i++) {
            const float gi = g[i];
            const float m0 = (i < LL - 3) ? fmaf(-gi, gi, gi)
                           : (i == LL - 3 ? tA : (i == LL - 2 ? tB : tC));
            float acc = fmaf(v3, m0, D[i]);
            acc = fmaf(v2, m1, acc);
            acc = fmaf(v1, m2, acc);
            g[i] = fmaf(v0, m3, acc);
            m3 = m2; m2 = m1; m1 = m0;
        }
    }

    // ---- registers -> smem (clipped) ----
    __syncthreads();
#pragma unroll
    for (int i = 0; i < LL; i++)
        st[w][lane * LL + i] = fminf(fmaxf(g[i], 1.0e-4f), 1.0f - 1.0e-4f);
    __syncthreads();

    // ---- smem -> global, skip halo ----
#pragma unroll
    for (int it = 0; it < TILE / 32; it++) {
        const int idx = it * (32 * WC) + tid;
        const int t = idx >> 3;
        const int c = idx & 7;
        const int gt = gt0 + t;
        if (t >= HALO && gt < Tdim)
            out[base + gt * Cdim + c0 + c] = st[c][t];
    }
}

extern "C" void kernel_launch(void* const* d_in, const int* in_sizes, int n_in,
                              void* d_out, int out_size)
{
    const float* drive = (const float*)d_in[0];
    const float* r     = (const float*)d_in[1];
    const float* eps   = (const float*)d_in[2];
    const float* beta  = (const float*)d_in[3];
    const float* Kc    = (const float*)d_in[4];
    float* out = (float*)d_out;

    dim3 grid(NTILES, Cdim / WC, Bdim);   // 6 x 64 x 4 = 1536 CTAs
    cml_kernel<<<grid, 32 * WC>>>(drive, r, eps, beta, Kc, out);
}

// round 10
// speedup vs baseline: 1.7974x; 1.0272x over previous
#include <cuda_runtime.h>
#include <cuda_bf16.h>

// CausalSequenceCML: 16 fused steps of depthwise-causal-conv logistic CML.
// B=4, T=4096, C=512, K=4, STEPS=16.
//
// Round-10: resubmit of R9 (round 9 died on a broker infra failure, not a
// kernel result). R3 skeleton (channel=lane, per-thread coeffs, smem
// boundary exchange — the only structure that sustains ~52% fma = 94% of
// the dedup-adjusted FFMA cap), with its geometry fixed:
//  - SS=16 strips x LL=19 cells, 512 threads. TILE=304, VALID=256,
//    NTILES=16 -> 16*256 = 4096 EXACT (zero tail waste), amp=1.1875.
//  - per-SM work ceil(1024/148)*304 = 2128 cell-units (R3: 2376, -10.4%).
//  - g[19]+D[19]=38 state regs, ~58 total: fits launch_bounds(512,2)
//    64-reg cap without spill. Occ 50%.
//  - phantom zero strip removes the s>0 branch.

#define Bdim 4
#define Tdim 4096
#define Cdim 512
#define NSTEPS 16
#define CC 32                // channels per block (warp-contiguous, lane=channel)
#define SS 16                // time strips per block
#define LL 19                // cells per thread
#define TILE (SS * LL)       // 304
#define HALO 48              // 3 * NSTEPS
#define VALID (TILE - HALO)  // 256
#define NTILES (Tdim / VALID) // 16, exact

__global__ void __launch_bounds__(CC * SS, 2)
cml_kernel(const float* __restrict__ drive,
           const float* __restrict__ r,
           const float* __restrict__ eps,
           const float* __restrict__ beta,
           const float* __restrict__ Kc,
           float* __restrict__ out)
{
    // boundary m' values, phantom zero strip at index 0: [buf][strip+1][3][ch]
    __shared__ float bm[2][SS + 1][3][CC];

    const int tid = threadIdx.x;
    const int c   = tid & (CC - 1);
    const int s   = tid >> 5;
    const int cg  = blockIdx.y * CC + c;
    const int b   = blockIdx.z;
    const int gt0 = (int)blockIdx.x * VALID - HALO;
    const int base = b * (Tdim * Cdim);

    // zero-pad phantom strip (both buffers)
    if (s == 0) {
#pragma unroll
        for (int j = 0; j < 3; j++) {
            bm[0][0][j][c] = 0.0f;
            bm[1][0][j][c] = 0.0f;
        }
    }

    // per-channel constants; fold r into the conv weights
    const float rr = r[cg];
    const float ee = eps[cg];
    const float bb = beta[cg];
    const float k0 = Kc[cg * 4 + 0];
    const float k1 = Kc[cg * 4 + 1];
    const float k2 = Kc[cg * 4 + 2];
    const float k3 = Kc[cg * 4 + 3];
    const float onemb = 1.0f - bb;
    const float A  = onemb * (1.0f - ee);
    const float Bc = onemb * ee;
    const float v3 = fmaf(Bc, k3, A) * rr;   // coeff of m'[t]
    const float v2 = Bc * k2 * rr;           // m'[t-1]
    const float v1 = Bc * k1 * rr;           // m'[t-2]
    const float v0 = Bc * k0 * rr;           // m'[t-3]

    // load drive -> g init, D = beta * drive (step-invariant, in regs)
    float g[LL], D[LL];
    const int ltbase = s * LL;
#pragma unroll
    for (int i = 0; i < LL; i++) {
        const int gt = gt0 + ltbase + i;
        float d = 0.0f;
        if (gt >= 0 && gt < Tdim)
            d = drive[base + gt * Cdim + cg];
        g[i] = d;
        D[i] = bb * d;
    }

#pragma unroll 1
    for (int step = 0; step < NSTEPS; step++) {
        float (*buf)[3][CC] = bm[step & 1];
        // boundary: m' of this strip's last 3 cells -> slot s+1
#pragma unroll
        for (int j = 0; j < 3; j++) {
            const float gi = g[LL - 3 + j];
            buf[s + 1][j][c] = fmaf(-gi, gi, gi);   // g*(1-g)
        }
        __syncthreads();

        float m3 = buf[s][0][c];
        float m2 = buf[s][1][c];
        float m1 = buf[s][2][c];
        // main sweep: 5 FMA ops per cell (m0's operand-dedup form is rt=1)
#pragma unroll
        for (int i = 0; i < LL; i++) {
            const float gi = g[i];
            const float m0 = fmaf(-gi, gi, gi);     // g*(1-g)
            float acc = fmaf(v3, m0, D[i]);
            acc = fmaf(v2, m1, acc);
            acc = fmaf(v1, m2, acc);
            g[i] = fmaf(v0, m3, acc);
            m3 = m2; m2 = m1; m1 = m0;
        }
    }

    // clip + store valid region (coalesced: lane = channel)
#pragma unroll
    for (int i = 0; i < LL; i++) {
        const int lt = ltbase + i;
        const int gt = gt0 + lt;
        if (lt >= HALO && gt < Tdim) {
            float v = fminf(fmaxf(g[i], 1.0e-4f), 1.0f - 1.0e-4f);
            out[base + gt * Cdim + cg] = v;
        }
    }
}

extern "C" void kernel_launch(void* const* d_in, const int* in_sizes, int n_in,
                              void* d_out, int out_size)
{
    const float* drive = (const float*)d_in[0];
    const float* r     = (const float*)d_in[1];
    const float* eps   = (const float*)d_in[2];
    const float* beta  = (const float*)d_in[3];
    const float* Kc    = (const float*)d_in[4];
    float* out = (float*)d_out;

    dim3 grid(NTILES, Cdim / CC, Bdim);   // 16 x 16 x 4 = 1024 CTAs
    cml_kernel<<<grid, CC * SS>>>(drive, r, eps, beta, Kc, out);
}

// round 11
// speedup vs baseline: 1.8176x; 1.0112x over previous
#include <cuda_runtime.h>
#include <cuda_bf16.h>

// CausalSequenceCML: 16 fused steps of depthwise-causal-conv logistic CML.
// B=4, T=4096, C=512, K=4, STEPS=16.
//
// Round-11: smem-exchange skeleton (the only one sustaining ~92% of the
// dedup-adjusted FFMA cap) at its best geometry that keeps occ>=3:
//  - SS=12 strips x LL=19 cells, 384 threads, launch_bounds(384,3):
//    TILE=228, VALID=180, NTILES=23 (grid 1472, 9.95 CTAs/SM -> balanced 10)
//    per-SM work 10*228 = 2280 cell-units (R3: 2376).
//  - 56-reg cap at occ 3: state g[19]+D[19]=38; boundary m' (tA/tB/tC)
//    reused in the sweep's last 3 cells via compile-time selection
//    (saves 3 FMAs/thread-step, no added live range).
//  - phantom zero strip (no s>0 branch), lean epilogue.

#define Bdim 4
#define Tdim 4096
#define Cdim 512
#define NSTEPS 16
#define CC 32                // channels per block (lane = channel)
#define SS 12                // time strips per block
#define LL 19                // cells per thread
#define TILE (SS * LL)       // 228
#define HALO 48              // 3 * NSTEPS
#define VALID (TILE - HALO)  // 180
#define NTILES ((Tdim + VALID - 1) / VALID)  // 23

__global__ void __launch_bounds__(CC * SS, 3)
cml_kernel(const float* __restrict__ drive,
           const float* __restrict__ r,
           const float* __restrict__ eps,
           const float* __restrict__ beta,
           const float* __restrict__ Kc,
           float* __restrict__ out)
{
    // boundary m' values, phantom zero strip at index 0: [buf][strip+1][3][ch]
    __shared__ float bm[2][SS + 1][3][CC];

    const int tid = threadIdx.x;
    const int c   = tid & (CC - 1);
    const int s   = tid >> 5;
    const int cg  = blockIdx.y * CC + c;
    const int b   = blockIdx.z;
    const int gt0 = (int)blockIdx.x * VALID - HALO;
    const int base = b * (Tdim * Cdim);

    // zero-pad phantom strip (both buffers)
    if (s == 0) {
#pragma unroll
        for (int j = 0; j < 3; j++) {
            bm[0][0][j][c] = 0.0f;
            bm[1][0][j][c] = 0.0f;
        }
    }

    // per-channel constants; fold r into the conv weights
    const float rr = r[cg];
    const float ee = eps[cg];
    const float bb = beta[cg];
    const float k0 = Kc[cg * 4 + 0];
    const float k1 = Kc[cg * 4 + 1];
    const float k2 = Kc[cg * 4 + 2];
    const float k3 = Kc[cg * 4 + 3];
    const float onemb = 1.0f - bb;
    const float A  = onemb * (1.0f - ee);
    const float Bc = onemb * ee;
    const float v3 = fmaf(Bc, k3, A) * rr;   // coeff of m'[t]
    const float v2 = Bc * k2 * rr;           // m'[t-1]
    const float v1 = Bc * k1 * rr;           // m'[t-2]
    const float v0 = Bc * k0 * rr;           // m'[t-3]

    // load drive -> g init, D = beta * drive (step-invariant, in regs)
    float g[LL], D[LL];
#pragma unroll
    for (int i = 0; i < LL; i++) {
        const int gt = gt0 + s * LL + i;
        float d = 0.0f;
        if (gt >= 0 && gt < Tdim)
            d = drive[base + gt * Cdim + cg];
        g[i] = d;
        D[i] = bb * d;
    }

#pragma unroll 1
    for (int step = 0; step < NSTEPS; step++) {
        float (*buf)[3][CC] = bm[step & 1];
        // boundary: m' of this strip's last 3 cells -> slot s+1 (kept live
        // and reused below for the sweep's last 3 cells)
        const float gA = g[LL - 3], gB = g[LL - 2], gC = g[LL - 1];
        const float tA = fmaf(-gA, gA, gA);
        const float tB = fmaf(-gB, gB, gB);
        const float tC = fmaf(-gC, gC, gC);
        buf[s + 1][0][c] = tA;
        buf[s + 1][1][c] = tB;
        buf[s + 1][2][c] = tC;
        __syncthreads();

        float m3 = buf[s][0][c];
        float m2 = buf[s][1][c];
        float m1 = buf[s][2][c];
        // main sweep: 5 FMA/cell; last-3 m' reused (compile-time select)
#pragma unroll
        for (int i = 0; i < LL; i++) {
            const float gi = g[i];
            const float m0 = (i < LL - 3) ? fmaf(-gi, gi, gi)
                           : (i == LL - 3 ? tA : (i == LL - 2 ? tB : tC));
            float acc = fmaf(v3, m0, D[i]);
            acc = fmaf(v2, m1, acc);
            acc = fmaf(v1, m2, acc);
            g[i] = fmaf(v0, m3, acc);
            m3 = m2; m2 = m1; m1 = m0;
        }
    }

    // clip + store valid region (coalesced: lane = channel)
#pragma unroll
    for (int i = 0; i < LL; i++) {
        const int lt = s * LL + i;
        const int gt = gt0 + lt;
        if (lt >= HALO && gt < Tdim) {
            const float v = fminf(fmaxf(g[i], 1.0e-4f), 1.0f - 1.0e-4f);
            out[base + gt * Cdim + cg] = v;
        }
    }
}

extern "C" void kernel_launch(void* const* d_in, const int* in_sizes, int n_in,
                              void* d_out, int out_size)
{
    const float* drive = (const float*)d_in[0];
    const float* r     = (const float*)d_in[1];
    const float* eps   = (const float*)d_in[2];
    const float* beta  = (const float*)d_in[3];
    const float* Kc    = (const float*)d_in[4];
    float* out = (float*)d_out;

    dim3 grid(NTILES, Cdim / CC, Bdim);   // 23 x 16 x 4 = 1472 CTAs
    cml_kernel<<<grid, CC * SS>>>(drive, r, eps, beta, Kc, out);
}

// round 12
// speedup vs baseline: 2.0565x; 1.1314x over previous
#include <cuda_runtime.h>
#include <cuda_bf16.h>

// CausalSequenceCML: 16 fused steps of depthwise-causal-conv logistic CML.
// B=4, T=4096, C=512, K=4, STEPS=16.
//
// Round-12: R11 skeleton (channel-per-thread, smem boundary exchange —
// runs at ~100% of the bank-limited FFMA rate) with the channel dim
// narrowed to widen time coverage per CTA:
//  - CC=8 channels x SS=48 strips x LL=12 cells, 384 threads, occ 3.
//  - TILE_T=576, VALID=528, NTILES=8: halo amp 1.031 (R11: 1.267).
//  - per-SM work 14 x (8x576) = 64512 cell-units (R11: 72960, -11.6%).
//  - state g[12]+D[12]=24 regs (~50 total): no spill at the occ-3 cap.
//  - smem exchange [2][49][3][8]: conflict-free (4 strips x 8 ch per warp
//    span all 32 banks). Global I/O: full 32B sectors, 4/warp-load.

#define Bdim 4
#define Tdim 4096
#define Cdim 512
#define NSTEPS 16
#define CC 8                 // channels per block (thread c = lane&7)
#define SS 48                // time strips per block
#define LL 12                // cells per thread
#define TILE (SS * LL)       // 576
#define HALO 48              // 3 * NSTEPS
#define VALID (TILE - HALO)  // 528
#define NTILES ((Tdim + VALID - 1) / VALID)  // 8

__global__ void __launch_bounds__(CC * SS, 3)
cml_kernel(const float* __restrict__ drive,
           const float* __restrict__ r,
           const float* __restrict__ eps,
           const float* __restrict__ beta,
           const float* __restrict__ Kc,
           float* __restrict__ out)
{
    // boundary m' values, phantom zero strip at index 0: [buf][strip+1][3][ch]
    __shared__ float bm[2][SS + 1][3][CC];

    const int tid = threadIdx.x;
    const int c   = tid & (CC - 1);
    const int s   = tid / CC;
    const int cg  = blockIdx.y * CC + c;
    const int b   = blockIdx.z;
    const int gt0 = (int)blockIdx.x * VALID - HALO;
    const int base = b * (Tdim * Cdim);

    // zero-pad phantom strip (both buffers)
    if (s == 0) {
#pragma unroll
        for (int j = 0; j < 3; j++) {
            bm[0][0][j][c] = 0.0f;
            bm[1][0][j][c] = 0.0f;
        }
    }

    // per-channel constants; fold r into the conv weights
    const float rr = r[cg];
    const float ee = eps[cg];
    const float bb = beta[cg];
    const float k0 = Kc[cg * 4 + 0];
    const float k1 = Kc[cg * 4 + 1];
    const float k2 = Kc[cg * 4 + 2];
    const float k3 = Kc[cg * 4 + 3];
    const float onemb = 1.0f - bb;
    const float A  = onemb * (1.0f - ee);
    const float Bc = onemb * ee;
    const float v3 = fmaf(Bc, k3, A) * rr;   // coeff of m'[t]
    const float v2 = Bc * k2 * rr;           // m'[t-1]
    const float v1 = Bc * k1 * rr;           // m'[t-2]
    const float v0 = Bc * k0 * rr;           // m'[t-3]

    // load drive -> g init, D = beta * drive (step-invariant, in regs)
    float g[LL], D[LL];
#pragma unroll
    for (int i = 0; i < LL; i++) {
        const int gt = gt0 + s * LL + i;
        float d = 0.0f;
        if (gt >= 0 && gt < Tdim)
            d = drive[base + gt * Cdim + cg];
        g[i] = d;
        D[i] = bb * d;
    }

#pragma unroll 1
    for (int step = 0; step < NSTEPS; step++) {
        float (*buf)[3][CC] = bm[step & 1];
        // boundary: m' of this strip's last 3 cells -> slot s+1 (kept live
        // and reused below for the sweep's last 3 cells)
        const float gA = g[LL - 3], gB = g[LL - 2], gC = g[LL - 1];
        const float tA = fmaf(-gA, gA, gA);
        const float tB = fmaf(-gB, gB, gB);
        const float tC = fmaf(-gC, gC, gC);
        buf[s + 1][0][c] = tA;
        buf[s + 1][1][c] = tB;
        buf[s + 1][2][c] = tC;
        __syncthreads();

        float m3 = buf[s][0][c];
        float m2 = buf[s][1][c];
        float m1 = buf[s][2][c];
        // main sweep: 5 FMA/cell; last-3 m' reused (compile-time select)
#pragma unroll
        for (int i = 0; i < LL; i++) {
            const float gi = g[i];
            const float m0 = (i < LL - 3) ? fmaf(-gi, gi, gi)
                           : (i == LL - 3 ? tA : (i == LL - 2 ? tB : tC));
            float acc = fmaf(v3, m0, D[i]);
            acc = fmaf(v2, m1, acc);
            acc = fmaf(v1, m2, acc);
            g[i] = fmaf(v0, m3, acc);
            m3 = m2; m2 = m1; m1 = m0;
        }
    }

    // clip + store valid region
#pragma unroll
    for (int i = 0; i < LL; i++) {
        const int lt = s * LL + i;
        const int gt = gt0 + lt;
        if (lt >= HALO && gt < Tdim) {
            const float v = fminf(fmaxf(g[i], 1.0e-4f), 1.0f - 1.0e-4f);
            out[base + gt * Cdim + cg] = v;
        }
    }
}

extern "C" void kernel_launch(void* const* d_in, const int* in_sizes, int n_in,
                              void* d_out, int out_size)
{
    const float* drive = (const float*)d_in[0];
    const float* r     = (const float*)d_in[1];
    const float* eps   = (const float*)d_in[2];
    const float* beta  = (const float*)d_in[3];
    const float* Kc    = (const float*)d_in[4];
    float* out = (float*)d_out;

    dim3 grid(NTILES, Cdim / CC, Bdim);   // 8 x 64 x 4 = 2048 CTAs
    cml_kernel<<<grid, CC * SS>>>(drive, r, eps, beta, Kc, out);
}